// round 3
// baseline (speedup 1.0000x reference)
#include <cuda_runtime.h>
#include <math.h>

#define B_    128
#define N_    4096
#define D_    384
#define K_    5
#define H1_   1024
#define H2_   512
#define XXDIM ((K_ + 1) * D_)   // 2304

// Scratch (no cudaMalloc allowed)
__device__ float g_sims[B_ * N_];
__device__ float g_xx[B_ * XXDIM];
__device__ float g_h1[B_ * H1_];
__device__ float g_h2[B_ * H1_];
__device__ float g_h3[B_ * H1_];
__device__ float g_h4[B_ * H2_];
__device__ float g_part[9 * B_ * H1_];

// completion counters (zero-init; every user resets after use -> graph-replay safe)
__device__ int g_cnt_sims[B_];
__device__ int g_cnt_l1[H1_ / 64];
__device__ int g_cnt_l2[H1_ / 64];
__device__ int g_cnt_l3[H1_ / 64];
__device__ int g_cnt_l4[H2_ / 64];
__device__ int g_cnt_fin;

// ---------------------------------------------------------------------------
// Kernel 1: sims + (last block per article) top-5 + gather
// grid = (8 chunks, 128 articles), block = 256
// ---------------------------------------------------------------------------
__global__ __launch_bounds__(256) void sims_topk_fused(
    const float* __restrict__ stance,
    const float* __restrict__ body,
    float* __restrict__ sims,
    float* __restrict__ xx)
{
    __shared__ float s_sims[N_];
    __shared__ int   s_idx[K_];
    __shared__ int   s_last;

    const int b     = blockIdx.y;
    const int chunk = blockIdx.x;
    const int tid   = threadIdx.x;
    const int lane  = tid & 31;
    const int warp  = tid >> 5;

    const float4* S = reinterpret_cast<const float4*>(stance + (size_t)b * D_);
    const float4 s0 = S[lane];
    const float4 s1 = S[lane + 32];
    const float4 s2 = S[lane + 64];

    const float4* Bp = reinterpret_cast<const float4*>(
        body + ((size_t)b * N_ + chunk * 512) * D_);
    float* out = sims + (size_t)b * N_ + chunk * 512;

    for (int n = warp * 2; n < 512; n += 16) {
        const float4* r0 = Bp + (size_t)n * 96;
        const float4* r1 = Bp + (size_t)(n + 1) * 96;
        float4 a0 = r0[lane], a1 = r0[lane + 32], a2 = r0[lane + 64];
        float4 c0 = r1[lane], c1 = r1[lane + 32], c2 = r1[lane + 64];

        float p = s0.x*a0.x + s0.y*a0.y + s0.z*a0.z + s0.w*a0.w
                + s1.x*a1.x + s1.y*a1.y + s1.z*a1.z + s1.w*a1.w
                + s2.x*a2.x + s2.y*a2.y + s2.z*a2.z + s2.w*a2.w;
        float q = s0.x*c0.x + s0.y*c0.y + s0.z*c0.z + s0.w*c0.w
                + s1.x*c1.x + s1.y*c1.y + s1.z*c1.z + s1.w*c1.w
                + s2.x*c2.x + s2.y*c2.y + s2.z*c2.z + s2.w*c2.w;
        #pragma unroll
        for (int o = 16; o > 0; o >>= 1) {
            p += __shfl_xor_sync(0xffffffffu, p, o);
            q += __shfl_xor_sync(0xffffffffu, q, o);
        }
        if (lane == 0) { out[n] = p; out[n + 1] = q; }
    }

    // completion detection for article b
    __threadfence();
    __syncthreads();
    if (tid == 0) s_last = (atomicAdd(&g_cnt_sims[b], 1) == 7) ? 1 : 0;
    __syncthreads();
    if (!s_last) return;

    // ---- last block: top-5 + gather (sims row is L2-hot) ----
    const float4* Sr = reinterpret_cast<const float4*>(sims + (size_t)b * N_);
    float4* Ss = reinterpret_cast<float4*>(s_sims);
    #pragma unroll
    for (int j = 0; j < 4; j++) Ss[tid + j * 256] = Sr[tid + j * 256];
    __syncthreads();

    if (warp == 0) {
        for (int r = 0; r < K_; r++) {
            float bv = -INFINITY;
            int   bi = N_;
            for (int n = lane; n < N_; n += 32) {
                float v = s_sims[n];
                if (v > bv) { bv = v; bi = n; }
            }
            #pragma unroll
            for (int o = 16; o > 0; o >>= 1) {
                float ov = __shfl_xor_sync(0xffffffffu, bv, o);
                int   oi = __shfl_xor_sync(0xffffffffu, bi, o);
                if (ov > bv || (ov == bv && oi < bi)) { bv = ov; bi = oi; }
            }
            if (lane == 0) { s_idx[r] = bi; s_sims[bi] = -INFINITY; }
            __syncwarp();
        }
        if (lane == 0) g_cnt_sims[b] = 0;   // reset for next replay
    }
    __syncthreads();

    float* xrow = xx + (size_t)b * XXDIM;
    for (int c = tid; c < D_; c += 256)
        xrow[c] = stance[(size_t)b * D_ + c];
    for (int e = tid; e < K_ * D_; e += 256) {
        int r = e / D_, c = e - r * D_;
        xrow[D_ + e] = body[((size_t)b * N_ + s_idx[r]) * D_ + c];
    }
}

// ---------------------------------------------------------------------------
// Split-K SGEMM with fused last-block reduction + bias + ReLU epilogue.
// grid = (N/64, S), block = 256, tile M=128 x N=64, microtile 8x4.
// If FINAL: after all n-blocks of this layer finish, the very last block also
// computes logits = h4 @ W5^T + b5.
// ---------------------------------------------------------------------------
template <int FINAL>
__global__ __launch_bounds__(256) void gemm_splitk_fused(
    const float* __restrict__ X, const float* __restrict__ W,
    const float* __restrict__ bias, float* __restrict__ part,
    float* __restrict__ Y, int N, int Kin, int kchunk, int S,
    int* __restrict__ cnt,
    const float* __restrict__ W5, const float* __restrict__ b5,
    float* __restrict__ outFinal)
{
    __shared__ float Xs[32][132];
    __shared__ float Ws[32][68];
    __shared__ int   s_last;

    const int t  = threadIdx.x;
    const int nb = blockIdx.x;
    const int n0 = nb * 64;
    const int ks = blockIdx.y * kchunk;
    const int tx = t & 15;
    const int ty = t >> 4;

    float acc[8][4];
    #pragma unroll
    for (int i = 0; i < 8; i++)
        #pragma unroll
        for (int j = 0; j < 4; j++) acc[i][j] = 0.f;

    for (int k0 = ks; k0 < ks + kchunk; k0 += 32) {
        #pragma unroll
        for (int j = 0; j < 4; j++) {
            int id = t + j * 256;
            int m  = id >> 3;
            int kv = id & 7;
            float4 v = *reinterpret_cast<const float4*>(&X[(size_t)m * Kin + k0 + kv * 4]);
            Xs[kv * 4 + 0][m] = v.x; Xs[kv * 4 + 1][m] = v.y;
            Xs[kv * 4 + 2][m] = v.z; Xs[kv * 4 + 3][m] = v.w;
        }
        #pragma unroll
        for (int j = 0; j < 2; j++) {
            int id = t + j * 256;
            int n  = id >> 3;
            int kv = id & 7;
            float4 v = *reinterpret_cast<const float4*>(&W[(size_t)(n0 + n) * Kin + k0 + kv * 4]);
            Ws[kv * 4 + 0][n] = v.x; Ws[kv * 4 + 1][n] = v.y;
            Ws[kv * 4 + 2][n] = v.z; Ws[kv * 4 + 3][n] = v.w;
        }
        __syncthreads();

        #pragma unroll
        for (int k = 0; k < 32; k++) {
            float4 a0 = *reinterpret_cast<const float4*>(&Xs[k][ty * 8]);
            float4 a1 = *reinterpret_cast<const float4*>(&Xs[k][ty * 8 + 4]);
            float4 b0 = *reinterpret_cast<const float4*>(&Ws[k][tx * 4]);
            float a[8]  = {a0.x, a0.y, a0.z, a0.w, a1.x, a1.y, a1.z, a1.w};
            float bb[4] = {b0.x, b0.y, b0.z, b0.w};
            #pragma unroll
            for (int i = 0; i < 8; i++)
                #pragma unroll
                for (int j = 0; j < 4; j++)
                    acc[i][j] = fmaf(a[i], bb[j], acc[i][j]);
        }
        __syncthreads();
    }

    float* pbase = part + ((size_t)blockIdx.y * B_) * N;
    #pragma unroll
    for (int i = 0; i < 8; i++) {
        int m = ty * 8 + i;
        *reinterpret_cast<float4*>(&pbase[(size_t)m * N + n0 + tx * 4]) =
            make_float4(acc[i][0], acc[i][1], acc[i][2], acc[i][3]);
    }

    // ---- completion detection for this n-block ----
    __threadfence();
    __syncthreads();
    if (t == 0) s_last = (atomicAdd(&cnt[nb], 1) == S - 1) ? 1 : 0;
    __syncthreads();
    if (!s_last) return;
    if (t == 0) cnt[nb] = 0;   // reset for replay

    // ---- reduce S partials + bias + ReLU for the 128x64 tile ----
    // 2048 float4 elements, 8 per thread
    #pragma unroll
    for (int j = 0; j < 8; j++) {
        int idx4 = t + j * 256;            // float4 index within tile
        int m    = (idx4 << 2) >> 6;       // /64
        int col  = (idx4 << 2) & 63;
        size_t off = (size_t)m * N + n0 + col;
        float4 s = *reinterpret_cast<const float4*>(&part[off]);
        for (int sp = 1; sp < S; sp++) {
            const float4 p = *reinterpret_cast<const float4*>(
                &part[(size_t)sp * B_ * N + off]);
            s.x += p.x; s.y += p.y; s.z += p.z; s.w += p.w;
        }
        const float4 bv = *reinterpret_cast<const float4*>(&bias[n0 + col]);
        s.x = fmaxf(s.x + bv.x, 0.f);
        s.y = fmaxf(s.y + bv.y, 0.f);
        s.z = fmaxf(s.z + bv.z, 0.f);
        s.w = fmaxf(s.w + bv.w, 0.f);
        *reinterpret_cast<float4*>(&Y[off]) = s;
    }

    if (FINAL) {
        // wait for all n-blocks of this layer, then compute logits
        __shared__ int s_fin;
        __threadfence();
        __syncthreads();
        if (t == 0) s_fin = (atomicAdd(&g_cnt_fin, 1) == (H2_ / 64) - 1) ? 1 : 0;
        __syncthreads();
        if (!s_fin) return;
        if (t == 0) g_cnt_fin = 0;

        const int m = t >> 1;
        const int c = t & 1;
        const float4* xr = reinterpret_cast<const float4*>(Y + (size_t)m * H2_);
        const float4* wr = reinterpret_cast<const float4*>(W5 + (size_t)c * H2_);
        float acc5 = 0.f;
        #pragma unroll 8
        for (int k = 0; k < H2_ / 4; k++) {
            float4 x = xr[k], w = wr[k];
            acc5 = fmaf(x.x, w.x, acc5); acc5 = fmaf(x.y, w.y, acc5);
            acc5 = fmaf(x.z, w.z, acc5); acc5 = fmaf(x.w, w.w, acc5);
        }
        outFinal[m * 2 + c] = acc5 + b5[c];
    }
}

// ---------------------------------------------------------------------------
extern "C" void kernel_launch(void* const* d_in, const int* in_sizes, int n_in,
                              void* d_out, int out_size)
{
    const float* stance = (const float*)d_in[0];
    const float* body   = (const float*)d_in[2];
    const float* W1 = (const float*)d_in[4];  const float* b1 = (const float*)d_in[5];
    const float* W2 = (const float*)d_in[6];  const float* b2 = (const float*)d_in[7];
    const float* W3 = (const float*)d_in[8];  const float* b3 = (const float*)d_in[9];
    const float* W4 = (const float*)d_in[10]; const float* b4 = (const float*)d_in[11];
    const float* W5 = (const float*)d_in[12]; const float* b5 = (const float*)d_in[13];

    float *sims, *xx, *h1, *h2, *h3, *h4, *part;
    int *c1, *c2, *c3, *c4;
    cudaGetSymbolAddress((void**)&sims, g_sims);
    cudaGetSymbolAddress((void**)&xx,   g_xx);
    cudaGetSymbolAddress((void**)&h1,   g_h1);
    cudaGetSymbolAddress((void**)&h2,   g_h2);
    cudaGetSymbolAddress((void**)&h3,   g_h3);
    cudaGetSymbolAddress((void**)&h4,   g_h4);
    cudaGetSymbolAddress((void**)&part, g_part);
    cudaGetSymbolAddress((void**)&c1,   g_cnt_l1);
    cudaGetSymbolAddress((void**)&c2,   g_cnt_l2);
    cudaGetSymbolAddress((void**)&c3,   g_cnt_l3);
    cudaGetSymbolAddress((void**)&c4,   g_cnt_l4);

    sims_topk_fused<<<dim3(8, B_), 256>>>(stance, body, sims, xx);

    gemm_splitk_fused<0><<<dim3(H1_ / 64, 9), 256>>>(
        xx, W1, b1, part, h1, H1_, XXDIM, 256, 9, c1, nullptr, nullptr, nullptr);
    gemm_splitk_fused<0><<<dim3(H1_ / 64, 8), 256>>>(
        h1, W2, b2, part, h2, H1_, H1_, 128, 8, c2, nullptr, nullptr, nullptr);
    gemm_splitk_fused<0><<<dim3(H1_ / 64, 8), 256>>>(
        h2, W3, b3, part, h3, H1_, H1_, 128, 8, c3, nullptr, nullptr, nullptr);
    gemm_splitk_fused<1><<<dim3(H2_ / 64, 16), 256>>>(
        h3, W4, b4, part, h4, H2_, H1_, 64, 16, c4, W5, b5, (float*)d_out);
}